// round 14
// baseline (speedup 1.0000x reference)
#include <cuda_runtime.h>
#include <cuda_bf16.h>
#include <math.h>
#include <stdint.h>

#define NNODES 50000
#define NEDGES 1600000
#define MPAD 50048     // 391 * 128
#define KP 512         // padded K for all big GEMMs
#define NPMAX 2048     // padded N max (L3)
#define SPLIT_R 25088  // 196 tiles * 128 — row split for overlap
#define MT_H0 196
#define MT_H1 195

// ---------------- scratch (static device globals; no allocation) ----------------
__device__ float g_bufA[(size_t)NNODES * 2000];   // 400 MB
__device__ float g_bufB[(size_t)NNODES * 2000];   // 400 MB
__device__ float g_bufS0[NNODES * 10];
__device__ float g_bufS1[NNODES * 10];
__device__ int   g_rowptr[NNODES + 1];
__device__ int   g_cursor[NNODES + 1];
__device__ int   g_cols[NEDGES];
__device__ float g_vals[NEDGES];
// bf16-split staging
__device__ __nv_bfloat16 g_Ahi[(size_t)MPAD * KP];
__device__ __nv_bfloat16 g_Alo[(size_t)MPAD * KP];
__device__ __nv_bfloat16 g_Bhi[(size_t)NPMAX * KP];
__device__ __nv_bfloat16 g_Blo[(size_t)NPMAX * KP];

// ---------------- PTX helpers (base sm_103-safe) --------------------------------
__device__ __forceinline__ uint32_t smem_u32(const void* p) {
    uint32_t a;
    asm("{ .reg .u64 t; cvta.to.shared.u64 t, %1; cvt.u32.u64 %0, t; }"
        : "=r"(a) : "l"(p));
    return a;
}
#define LDSM4(r, addr)                                                          \
    asm volatile("ldmatrix.sync.aligned.m8n8.x4.shared.b16 {%0,%1,%2,%3}, [%4];" \
                 : "=r"((r)[0]), "=r"((r)[1]), "=r"((r)[2]), "=r"((r)[3])       \
                 : "r"(addr))
#define LDSM2(r, addr)                                                          \
    asm volatile("ldmatrix.sync.aligned.m8n8.x2.shared.b16 {%0,%1}, [%2];"      \
                 : "=r"((r)[0]), "=r"((r)[1])                                   \
                 : "r"(addr))
#define MMA_BF16(d, a, b)                                                       \
    asm volatile(                                                               \
        "mma.sync.aligned.m16n8k16.row.col.f32.bf16.bf16.f32 "                  \
        "{%0,%1,%2,%3}, {%4,%5,%6,%7}, {%8,%9}, {%0,%1,%2,%3};"                 \
        : "+f"((d)[0]), "+f"((d)[1]), "+f"((d)[2]), "+f"((d)[3])                \
        : "r"((a)[0]), "r"((a)[1]), "r"((a)[2]), "r"((a)[3]),                   \
          "r"((b)[0]), "r"((b)[1]))
#define CP_ASYNC16(saddr, gptr)                                                 \
    asm volatile("cp.async.cg.shared.global [%0], [%1], 16;" ::                 \
                 "r"(saddr), "l"(gptr))
#define CP_COMMIT() asm volatile("cp.async.commit_group;" ::: "memory")
#define CP_WAIT(n) asm volatile("cp.async.wait_group %0;" :: "n"(n) : "memory")

// ---------------- CSR build --------------------------------------------------
__global__ void k_zero_counts() {
    for (int i = blockIdx.x * blockDim.x + threadIdx.x; i <= NNODES;
         i += gridDim.x * blockDim.x)
        g_cursor[i] = 0;
}
__global__ void k_hist(const int* __restrict__ row) {
    for (int e = blockIdx.x * blockDim.x + threadIdx.x; e < NEDGES;
         e += gridDim.x * blockDim.x)
        atomicAdd(&g_cursor[row[e]], 1);
}
__global__ void k_scan() {
    __shared__ int s[1024];
    const int CH = (NNODES + 1023) / 1024;
    int t = threadIdx.x;
    int beg = t * CH;
    int end = min(NNODES, beg + CH);
    int mysum = 0;
    for (int i = beg; i < end; i++) mysum += g_cursor[i];
    s[t] = mysum;
    __syncthreads();
    for (int off = 1; off < 1024; off <<= 1) {
        int v = (t >= off) ? s[t - off] : 0;
        __syncthreads();
        s[t] += v;
        __syncthreads();
    }
    int run = s[t] - mysum;
    for (int i = beg; i < end; i++) {
        g_rowptr[i] = run;
        run += g_cursor[i];
    }
    if (t == 1023) g_rowptr[NNODES] = s[1023];
}
__global__ void k_reset_cursor() {
    for (int i = blockIdx.x * blockDim.x + threadIdx.x; i <= NNODES;
         i += gridDim.x * blockDim.x)
        g_cursor[i] = g_rowptr[i];
}
__global__ void k_scatter(const int* __restrict__ row, const int* __restrict__ col,
                          const float* __restrict__ vals) {
    for (int e = blockIdx.x * blockDim.x + threadIdx.x; e < NEDGES;
         e += gridDim.x * blockDim.x) {
        int p = atomicAdd(&g_cursor[row[e]], 1);
        g_cols[p] = col[e];
        g_vals[p] = vals[e];
    }
}

// ---------------- bf16 split converts ---------------------------------------
__global__ void k_convA(const float* __restrict__ src, const float* __restrict__ mix,
                        int M, int K) {
    int idx = blockIdx.x * blockDim.x + threadIdx.x;
    int m = idx >> 8;
    int k2 = (idx & 255) * 2;
    if (m >= MPAD) return;
    float v0 = 0.f, v1 = 0.f;
    if (m < M) {
        if (k2 < K) v0 = src[(size_t)m * K + k2];
        if (k2 + 1 < K) v1 = src[(size_t)m * K + k2 + 1];
        if (mix) {
            if (k2 < K) v0 = 0.5f * (v0 + mix[(size_t)m * K + k2]);
            if (k2 + 1 < K) v1 = 0.5f * (v1 + mix[(size_t)m * K + k2 + 1]);
        }
    }
    __nv_bfloat16 h0 = __float2bfloat16(v0);
    __nv_bfloat16 h1 = __float2bfloat16(v1);
    __nv_bfloat16 l0 = __float2bfloat16(v0 - __bfloat162float(h0));
    __nv_bfloat16 l1 = __float2bfloat16(v1 - __bfloat162float(h1));
    size_t o = ((size_t)m * KP + k2) >> 1;
    __nv_bfloat162* ph = (__nv_bfloat162*)g_Ahi;
    __nv_bfloat162* pl = (__nv_bfloat162*)g_Alo;
    ph[o] = __nv_bfloat162(h0, h1);
    pl[o] = __nv_bfloat162(l0, l1);
}

__global__ void k_convB(const float* __restrict__ W, int K, int N, int NP) {
    int idx = blockIdx.x * blockDim.x + threadIdx.x;
    int n = idx >> 9;
    int k = idx & (KP - 1);
    if (n >= NP) return;
    float v = (n < N && k < K) ? W[(size_t)k * N + n] : 0.f;
    __nv_bfloat16 h = __float2bfloat16(v);
    __nv_bfloat16 l = __float2bfloat16(v - __bfloat162float(h));
    g_Bhi[(size_t)n * KP + k] = h;
    g_Blo[(size_t)n * KP + k] = l;
}

// ---------------- HMMA bf16x3 GEMM, cp.async double-buffered ------------------
// Block 128x128, BK=32, 8 warps (2M x 4N), warp tile 64x32, mma m16n8k16.
#define GBM 128
#define GBN 128
#define STG_SZ 10240
#define OFF_AHI 0
#define OFF_ALO 20480
#define OFF_BHI 40960
#define OFF_BLO 61440
#define SM_TOTAL 81920

__global__ void __launch_bounds__(256, 2)
k_mma(const __nv_bfloat16* __restrict__ Ahi, const __nv_bfloat16* __restrict__ Alo,
      const __nv_bfloat16* __restrict__ Bhi, const __nv_bfloat16* __restrict__ Blo,
      float* __restrict__ C, int Mact, int Nact, int relu, int tileOff) {
    extern __shared__ char smem[];
    uint32_t sb = smem_u32(smem);

    int tid = threadIdx.x, lane = tid & 31, w = tid >> 5;
    int wm = w >> 2, wn = w & 3;
    int rowBase = (blockIdx.y + tileOff) * GBM, colBase = blockIdx.x * GBN;

    float acc[4][4][4];
#pragma unroll
    for (int i = 0; i < 4; i++)
#pragma unroll
        for (int j = 0; j < 4; j++)
#pragma unroll
            for (int c = 0; c < 4; c++) acc[i][j][c] = 0.f;

    int arow = lane & 15;
    int acolH = (lane >> 4) * 8;
    int l16 = lane & 15;
    int brow = l16 & 7;
    int bcolH = (l16 >> 3) * 8;

    int lr0 = tid >> 2;
    int lk = (tid & 3) * 16;

#define LOAD_CHUNK(ch, stg)                                                     \
    {                                                                           \
        int k0 = (ch) * 32;                                                     \
        _Pragma("unroll")                                                       \
        for (int it = 0; it < 2; it++) {                                        \
            int r = it * 64 + lr0;                                              \
            uint32_t so = (stg) * STG_SZ + r * 80 + lk;                         \
            const char* gh = (const char*)(Ahi + (size_t)(rowBase + r) * KP + k0); \
            const char* gl = (const char*)(Alo + (size_t)(rowBase + r) * KP + k0); \
            CP_ASYNC16(sb + OFF_AHI + so, gh + lk);                             \
            CP_ASYNC16(sb + OFF_ALO + so, gl + lk);                             \
            const char* bh_ = (const char*)(Bhi + (size_t)(colBase + r) * KP + k0); \
            const char* bl_ = (const char*)(Blo + (size_t)(colBase + r) * KP + k0); \
            CP_ASYNC16(sb + OFF_BHI + so, bh_ + lk);                            \
            CP_ASYNC16(sb + OFF_BLO + so, bl_ + lk);                            \
        }                                                                       \
    }

    LOAD_CHUNK(0, 0);
    CP_COMMIT();

    for (int ch = 0; ch < 16; ch++) {
        int cur = ch & 1;
        if (ch + 1 < 16) {
            LOAD_CHUNK(ch + 1, cur ^ 1);
            CP_COMMIT();
            CP_WAIT(1);
        } else {
            CP_WAIT(0);
        }
        __syncthreads();
        uint32_t aHiB = sb + OFF_AHI + cur * STG_SZ;
        uint32_t aLoB = sb + OFF_ALO + cur * STG_SZ;
        uint32_t bHiB = sb + OFF_BHI + cur * STG_SZ;
        uint32_t bLoB = sb + OFF_BLO + cur * STG_SZ;
#pragma unroll
        for (int kk = 0; kk < 2; kk++) {
            int kbase = kk * 16;
            uint32_t ah[4][4], al[4][4], bh[4][2], bl[4][2];
#pragma unroll
            for (int mt = 0; mt < 4; mt++) {
                uint32_t ro = (wm * 64 + mt * 16 + arow) * 80 +
                              (kbase + acolH) * 2;
                LDSM4(ah[mt], aHiB + ro);
                LDSM4(al[mt], aLoB + ro);
            }
#pragma unroll
            for (int nt = 0; nt < 4; nt++) {
                uint32_t ro = (wn * 32 + nt * 8 + brow) * 80 +
                              (kbase + bcolH) * 2;
                LDSM2(bh[nt], bHiB + ro);
                LDSM2(bl[nt], bLoB + ro);
            }
#pragma unroll
            for (int mt = 0; mt < 4; mt++)
#pragma unroll
                for (int nt = 0; nt < 4; nt++) {
                    MMA_BF16(acc[mt][nt], ah[mt], bh[nt]);
                    MMA_BF16(acc[mt][nt], ah[mt], bl[nt]);
                    MMA_BF16(acc[mt][nt], al[mt], bh[nt]);
                }
        }
        __syncthreads();
    }
#undef LOAD_CHUNK

#pragma unroll
    for (int mt = 0; mt < 4; mt++) {
#pragma unroll
        for (int nt = 0; nt < 4; nt++) {
            int r0 = rowBase + wm * 64 + mt * 16 + (lane >> 2);
            int c0 = colBase + wn * 32 + nt * 8 + (lane & 3) * 2;
            float* a = acc[mt][nt];
            if (relu) {
                a[0] = fmaxf(a[0], 0.f);
                a[1] = fmaxf(a[1], 0.f);
                a[2] = fmaxf(a[2], 0.f);
                a[3] = fmaxf(a[3], 0.f);
            }
            if (r0 < Mact && c0 + 1 < Nact)
                *(float2*)(C + (size_t)r0 * Nact + c0) = make_float2(a[0], a[1]);
            else if (r0 < Mact && c0 < Nact)
                C[(size_t)r0 * Nact + c0] = a[0];
            int r1 = r0 + 8;
            if (r1 < Mact && c0 + 1 < Nact)
                *(float2*)(C + (size_t)r1 * Nact + c0) = make_float2(a[2], a[3]);
            else if (r1 < Mact && c0 < Nact)
                C[(size_t)r1 * Nact + c0] = a[2];
        }
    }
}

// ---------------- SpMM width-500 -> fp32 out, fused relu+mix ------------------
__global__ void __launch_bounds__(128)
k_spmm_w500(const float* __restrict__ Min, const float* __restrict__ mix,
            float* __restrict__ Mout, int relu, int rowOff) {
    const int W = 500;
    int r = blockIdx.x + rowOff;
    int t = threadIdx.x;
    int start = g_rowptr[r], end = g_rowptr[r + 1];
    float4 acc = make_float4(0.f, 0.f, 0.f, 0.f);
    __shared__ int scol[128];
    __shared__ float sval[128];
    for (int e0 = start; e0 < end; e0 += 128) {
        int n = min(128, end - e0);
        if (t < n) {
            scol[t] = g_cols[e0 + t];
            sval[t] = g_vals[e0 + t];
        }
        __syncthreads();
        if (t < 125) {
            for (int i = 0; i < n; i++) {
                const float4* p = (const float4*)(Min + (size_t)scol[i] * W) + t;
                float v = sval[i];
                float4 x = *p;
                acc.x += v * x.x;
                acc.y += v * x.y;
                acc.z += v * x.z;
                acc.w += v * x.w;
            }
        }
        __syncthreads();
    }
    if (t < 125) {
        if (relu) {
            acc.x = fmaxf(acc.x, 0.f);
            acc.y = fmaxf(acc.y, 0.f);
            acc.z = fmaxf(acc.z, 0.f);
            acc.w = fmaxf(acc.w, 0.f);
        }
        if (mix) {
            float4 mx = *((const float4*)(mix + (size_t)r * W) + t);
            acc.x = 0.5f * (acc.x + mx.x);
            acc.y = 0.5f * (acc.y + mx.y);
            acc.z = 0.5f * (acc.z + mx.z);
            acc.w = 0.5f * (acc.w + mx.w);
        }
        *((float4*)(Mout + (size_t)r * W) + t) = acc;
    }
}

// ---------------- SpMM width-500 -> bf16 hi/lo split out, fused relu+mix ------
__global__ void __launch_bounds__(128)
k_spmm_w500_split(const float* __restrict__ Min, const float* __restrict__ mix,
                  int relu, int rowOff) {
    const int W = 500;
    int r = blockIdx.x + rowOff;
    int t = threadIdx.x;
    int start = g_rowptr[r], end = g_rowptr[r + 1];
    float4 acc = make_float4(0.f, 0.f, 0.f, 0.f);
    __shared__ int scol[128];
    __shared__ float sval[128];
    for (int e0 = start; e0 < end; e0 += 128) {
        int n = min(128, end - e0);
        if (t < n) {
            scol[t] = g_cols[e0 + t];
            sval[t] = g_vals[e0 + t];
        }
        __syncthreads();
        if (t < 125) {
            for (int i = 0; i < n; i++) {
                const float4* p = (const float4*)(Min + (size_t)scol[i] * W) + t;
                float v = sval[i];
                float4 x = *p;
                acc.x += v * x.x;
                acc.y += v * x.y;
                acc.z += v * x.z;
                acc.w += v * x.w;
            }
        }
        __syncthreads();
    }
    __nv_bfloat162* ph = (__nv_bfloat162*)(g_Ahi + (size_t)r * KP);
    __nv_bfloat162* pl = (__nv_bfloat162*)(g_Alo + (size_t)r * KP);
    if (t < 125) {
        if (relu) {
            acc.x = fmaxf(acc.x, 0.f);
            acc.y = fmaxf(acc.y, 0.f);
            acc.z = fmaxf(acc.z, 0.f);
            acc.w = fmaxf(acc.w, 0.f);
        }
        if (mix) {
            float4 mx = *((const float4*)(mix + (size_t)r * W) + t);
            acc.x = 0.5f * (acc.x + mx.x);
            acc.y = 0.5f * (acc.y + mx.y);
            acc.z = 0.5f * (acc.z + mx.z);
            acc.w = 0.5f * (acc.w + mx.w);
        }
        __nv_bfloat16 h0 = __float2bfloat16(acc.x);
        __nv_bfloat16 h1 = __float2bfloat16(acc.y);
        __nv_bfloat16 h2 = __float2bfloat16(acc.z);
        __nv_bfloat16 h3 = __float2bfloat16(acc.w);
        ph[2 * t + 0] = __nv_bfloat162(h0, h1);
        ph[2 * t + 1] = __nv_bfloat162(h2, h3);
        pl[2 * t + 0] = __nv_bfloat162(
            __float2bfloat16(acc.x - __bfloat162float(h0)),
            __float2bfloat16(acc.y - __bfloat162float(h1)));
        pl[2 * t + 1] = __nv_bfloat162(
            __float2bfloat16(acc.z - __bfloat162float(h2)),
            __float2bfloat16(acc.w - __bfloat162float(h3)));
    } else {
        __nv_bfloat162 zz(__float2bfloat16(0.f), __float2bfloat16(0.f));
        ph[2 * t + 0] = zz;
        ph[2 * t + 1] = zz;
        pl[2 * t + 0] = zz;
        pl[2 * t + 1] = zz;
    }
}

// ---------------- SpMM width-10 -----------------------------------------------
__global__ void k_spmm_w10(const float* __restrict__ Min, float* __restrict__ Mout,
                           int relu) {
    int r = blockIdx.x * blockDim.x + threadIdx.x;
    if (r >= NNODES) return;
    float acc[10];
#pragma unroll
    for (int j = 0; j < 10; j++) acc[j] = 0.f;
    int start = g_rowptr[r], end = g_rowptr[r + 1];
    for (int e = start; e < end; e++) {
        int c = g_cols[e];
        float v = g_vals[e];
        const float2* p = (const float2*)(Min + (size_t)c * 10);
#pragma unroll
        for (int j = 0; j < 5; j++) {
            float2 x = p[j];
            acc[2 * j + 0] += v * x.x;
            acc[2 * j + 1] += v * x.y;
        }
    }
    float* o = Mout + (size_t)r * 10;
#pragma unroll
    for (int j = 0; j < 10; j++) o[j] = relu ? fmaxf(acc[j], 0.f) : acc[j];
}

// ---------------- thin GEMM layer4 ----------------------------------------------
__global__ void __launch_bounds__(256)
k_gemm_thin(const float* __restrict__ Hin, const float* __restrict__ Tmix,
            const float* __restrict__ W4, float* __restrict__ Mout, int blkOff) {
    const int K = 2000, CHUNK = 1000;
    __shared__ float Ws[CHUNK * 10];
    int tid = threadIdx.x;
    int r = (blockIdx.x + blkOff) * 256 + tid;
    float acc[10];
#pragma unroll
    for (int j = 0; j < 10; j++) acc[j] = 0.f;
    for (int k0 = 0; k0 < K; k0 += CHUNK) {
        __syncthreads();
        for (int i = tid; i < CHUNK * 10; i += 256) Ws[i] = W4[k0 * 10 + i];
        __syncthreads();
        if (r < NNODES) {
            const float* hrow = Hin + (size_t)r * K + k0;
            const float* trow = Tmix + (size_t)r * K + k0;
            for (int k = 0; k < CHUNK; k += 4) {
                float4 h = *(const float4*)(hrow + k);
                float4 t = *(const float4*)(trow + k);
                float a0 = 0.5f * (h.x + t.x);
                float a1 = 0.5f * (h.y + t.y);
                float a2 = 0.5f * (h.z + t.z);
                float a3 = 0.5f * (h.w + t.w);
#pragma unroll
                for (int j = 0; j < 10; j++)
                    acc[j] += a0 * Ws[(k + 0) * 10 + j] + a1 * Ws[(k + 1) * 10 + j] +
                              a2 * Ws[(k + 2) * 10 + j] + a3 * Ws[(k + 3) * 10 + j];
            }
        }
    }
    if (r < NNODES) {
        float* o = Mout + (size_t)r * 10;
#pragma unroll
        for (int j = 0; j < 10; j++) o[j] = acc[j];
    }
}

// ---------------- tiny GEMM layer5 ----------------------------------------------
__global__ void k_gemm5(const float* __restrict__ Hin, const float* __restrict__ Zmix,
                        const float* __restrict__ W5, float* __restrict__ Mout) {
    __shared__ float Ws[100];
    int t = threadIdx.x;
    if (t < 100) Ws[t] = W5[t];
    __syncthreads();
    int r = blockIdx.x * blockDim.x + t;
    if (r >= NNODES) return;
    float a[10];
#pragma unroll
    for (int k = 0; k < 10; k++)
        a[k] = 0.5f * (Hin[(size_t)r * 10 + k] + Zmix[(size_t)r * 10 + k]);
    float* o = Mout + (size_t)r * 10;
#pragma unroll
    for (int j = 0; j < 10; j++) {
        float s = 0.f;
#pragma unroll
        for (int k = 0; k < 10; k++) s += a[k] * Ws[k * 10 + j];
        o[j] = s;
    }
}

// ---------------- row softmax over width 10 --------------------------------------
__global__ void k_softmax(const float* __restrict__ S, float* __restrict__ out) {
    int r = blockIdx.x * blockDim.x + threadIdx.x;
    if (r >= NNODES) return;
    float v[10];
    float m = -1e30f;
#pragma unroll
    for (int j = 0; j < 10; j++) {
        v[j] = S[(size_t)r * 10 + j];
        m = fmaxf(m, v[j]);
    }
    float sum = 0.f;
#pragma unroll
    for (int j = 0; j < 10; j++) {
        v[j] = expf(v[j] - m);
        sum += v[j];
    }
    float inv = 1.f / sum;
#pragma unroll
    for (int j = 0; j < 10; j++) out[(size_t)r * 10 + j] = v[j] * inv;
}

// ---------------- launch ---------------------------------------------------------
extern "C" void kernel_launch(void* const* d_in, const int* in_sizes, int n_in,
                              void* d_out, int out_size) {
    const float* x    = (const float*)d_in[0];
    const float* tra1 = (const float*)d_in[1];
    const float* tra2 = (const float*)d_in[2];
    const float* tra3 = (const float*)d_in[3];
    const float* z    = (const float*)d_in[4];
    const float* evals = (const float*)d_in[5];
    const int*   row  = (const int*)d_in[6];
    const int*   col  = (const int*)d_in[7];
    const float* W1 = (const float*)d_in[8];
    const float* W2 = (const float*)d_in[9];
    const float* W3 = (const float*)d_in[10];
    const float* W4 = (const float*)d_in[11];
    const float* W5 = (const float*)d_in[12];
    float* out = (float*)d_out;

    float *bufA, *bufB, *bufS0, *bufS1;
    __nv_bfloat16 *Ahi, *Alo, *Bhi, *Blo;
    cudaGetSymbolAddress((void**)&bufA, g_bufA);
    cudaGetSymbolAddress((void**)&bufB, g_bufB);
    cudaGetSymbolAddress((void**)&bufS0, g_bufS0);
    cudaGetSymbolAddress((void**)&bufS1, g_bufS1);
    cudaGetSymbolAddress((void**)&Ahi, g_Ahi);
    cudaGetSymbolAddress((void**)&Alo, g_Alo);
    cudaGetSymbolAddress((void**)&Bhi, g_Bhi);
    cudaGetSymbolAddress((void**)&Blo, g_Blo);

    cudaFuncSetAttribute(k_mma, cudaFuncAttributeMaxDynamicSharedMemorySize,
                         SM_TOTAL);

    // side stream + events (fresh per call; host-side handles only, no device mem)
    cudaStream_t s1;
    cudaStreamCreateWithFlags(&s1, cudaStreamNonBlocking);
    cudaEvent_t ev[10];
    for (int i = 0; i < 10; i++)
        cudaEventCreateWithFlags(&ev[i], cudaEventDisableTiming);

    const int H1R = NNODES - SPLIT_R;  // 24912

    // fork s1 from main
    cudaEventRecord(ev[0], 0);
    cudaStreamWaitEvent(s1, ev[0], 0);

    // main: L1 prep + GEMM L1 (k_mma is 4th launch — ncu capture slot)
    k_convA<<<MPAD, 256>>>(x, nullptr, NNODES, 512);
    k_convB<<<1024, 256>>>(W1, 512, 500, 512);
    k_zero_counts<<<64, 256, 0, s1>>>();
    k_mma<<<dim3(4, 391), 256, SM_TOTAL>>>(Ahi, Alo, Bhi, Blo, bufA,
                                           NNODES, 500, 0, 0);
    // s1: rest of CSR build (overlaps GEMM L1)
    k_hist<<<2048, 256, 0, s1>>>(row);
    k_scan<<<1, 1024, 0, s1>>>();
    k_reset_cursor<<<64, 256, 0, s1>>>();
    k_scatter<<<2048, 256, 0, s1>>>(row, col, evals);
    cudaEventRecord(ev[1], s1);              // CSR done

    // main: W2 conversion (after L1 GEMM consumed W1 tiles)
    k_convB<<<1024, 256>>>(W2, 500, 500, 512);
    cudaStreamWaitEvent(0, ev[1], 0);        // main now has CSR
    cudaEventRecord(ev[2], 0);
    cudaStreamWaitEvent(s1, ev[2], 0);

    // s1: spmm_split1 h1  ||  main: spmm_split1 h0 + GEMM L2 h0
    k_spmm_w500_split<<<H1R, 128, 0, s1>>>(bufA, tra1, 1, SPLIT_R);
    cudaEventRecord(ev[3], s1);
    k_spmm_w500_split<<<SPLIT_R, 128>>>(bufA, tra1, 1, 0);
    k_mma<<<dim3(4, MT_H0), 256, SM_TOTAL>>>(Ahi, Alo, Bhi, Blo, bufB,
                                             NNODES, 500, 0, 0);
    cudaStreamWaitEvent(0, ev[3], 0);
    k_mma<<<dim3(4, MT_H1), 256, SM_TOTAL>>>(Ahi, Alo, Bhi, Blo, bufB,
                                             NNODES, 500, 0, MT_H0);
    cudaEventRecord(ev[4], 0);               // GEMM L2 fully issued
    cudaStreamWaitEvent(s1, ev[4], 0);
    // s1: W3 conversion (overlaps spmm_tra2 on main)
    k_convB<<<4096, 256, 0, s1>>>(W3, 500, 2000, 2048);
    cudaEventRecord(ev[5], s1);

    // main: M3 = 0.5*(relu(spmm(B2)) + tra2)  (bufB -> bufA, full)
    k_spmm_w500<<<NNODES, 128>>>(bufB, tra2, bufA, 1, 0);
    // main: split3 h0 (bufA -> g_Ahi/g_Alo)
    k_spmm_w500_split<<<SPLIT_R, 128>>>(bufA, nullptr, 0, 0);
    cudaEventRecord(ev[6], 0);
    cudaStreamWaitEvent(s1, ev[6], 0);
    // s1: split3 h1  ||  main: GEMM L3 h0
    k_spmm_w500_split<<<H1R, 128, 0, s1>>>(bufA, nullptr, 0, SPLIT_R);
    cudaEventRecord(ev[7], s1);

    cudaStreamWaitEvent(0, ev[5], 0);        // W3 ready
    k_mma<<<dim3(16, MT_H0), 256, SM_TOTAL>>>(Ahi, Alo, Bhi, Blo, bufB,
                                              NNODES, 2000, 1, 0);
    cudaStreamWaitEvent(0, ev[7], 0);
    cudaEventRecord(ev[8], 0);
    cudaStreamWaitEvent(s1, ev[8], 0);
    // s1: GEMM L3 h1  ||  main: gemm_thin h0
    k_mma<<<dim3(16, MT_H1), 256, SM_TOTAL, s1>>>(Ahi, Alo, Bhi, Blo, bufB,
                                                  NNODES, 2000, 1, MT_H0);
    cudaEventRecord(ev[9], s1);

    k_gemm_thin<<<98, 256>>>(bufB, tra3, W4, bufS0, 0);    // rows [0, 25088)
    cudaStreamWaitEvent(0, ev[9], 0);
    k_gemm_thin<<<98, 256>>>(bufB, tra3, W4, bufS0, 98);   // rows [25088, 50000)

    // L4/L5 tails (serial, tiny)
    k_spmm_w10<<<(NNODES + 255) / 256, 256>>>(bufS0, bufS1, 1);
    k_gemm5<<<(NNODES + 255) / 256, 256>>>(bufS1, z, W5, bufS0);
    k_spmm_w10<<<(NNODES + 255) / 256, 256>>>(bufS0, bufS1, 0);
    k_softmax<<<(NNODES + 255) / 256, 256>>>(bufS1, out);
}

// round 16
// speedup vs baseline: 1.2355x; 1.2355x over previous
#include <cuda_runtime.h>
#include <cuda_bf16.h>
#include <math.h>
#include <stdint.h>

#define NNODES 50000
#define NEDGES 1600000
#define MPAD 50048     // 391 * 128
#define KP 512         // padded K for all big GEMMs
#define GP 512         // bf16 gather-buffer row stride

// ---------------- scratch (static device globals; no allocation) ----------------
__device__ float g_bufA[(size_t)NNODES * 2000];   // 400 MB (L3 fp32 out)
__device__ float g_bufS0[NNODES * 10];
__device__ float g_bufS1[NNODES * 10];
__device__ int   g_rowptr[NNODES + 1];
__device__ int   g_cursor[NNODES + 1];
__device__ int   g_cols[NEDGES];
__device__ float g_vals[NEDGES];
// bf16-split staging (GEMM A operands)
__device__ __nv_bfloat16 g_Ahi[(size_t)MPAD * KP];
__device__ __nv_bfloat16 g_Alo[(size_t)MPAD * KP];
__device__ __nv_bfloat16 g_Bhi[(size_t)2048 * KP];
__device__ __nv_bfloat16 g_Blo[(size_t)2048 * KP];
// bf16 gather buffers (SpMM inputs)
__device__ __nv_bfloat16 g_G[(size_t)NNODES * GP];    // 51.2 MB
__device__ __nv_bfloat16 g_G2[(size_t)NNODES * GP];   // 51.2 MB

// ---------------- PTX helpers (base sm_103-safe) --------------------------------
__device__ __forceinline__ uint32_t smem_u32(const void* p) {
    uint32_t a;
    asm("{ .reg .u64 t; cvta.to.shared.u64 t, %1; cvt.u32.u64 %0, t; }"
        : "=r"(a) : "l"(p));
    return a;
}
#define LDSM4(r, addr)                                                          \
    asm volatile("ldmatrix.sync.aligned.m8n8.x4.shared.b16 {%0,%1,%2,%3}, [%4];" \
                 : "=r"((r)[0]), "=r"((r)[1]), "=r"((r)[2]), "=r"((r)[3])       \
                 : "r"(addr))
#define LDSM2(r, addr)                                                          \
    asm volatile("ldmatrix.sync.aligned.m8n8.x2.shared.b16 {%0,%1}, [%2];"      \
                 : "=r"((r)[0]), "=r"((r)[1])                                   \
                 : "r"(addr))
#define MMA_BF16(d, a, b)                                                       \
    asm volatile(                                                               \
        "mma.sync.aligned.m16n8k16.row.col.f32.bf16.bf16.f32 "                  \
        "{%0,%1,%2,%3}, {%4,%5,%6,%7}, {%8,%9}, {%0,%1,%2,%3};"                 \
        : "+f"((d)[0]), "+f"((d)[1]), "+f"((d)[2]), "+f"((d)[3])                \
        : "r"((a)[0]), "r"((a)[1]), "r"((a)[2]), "r"((a)[3]),                   \
          "r"((b)[0]), "r"((b)[1]))
#define CP_ASYNC16(saddr, gptr)                                                 \
    asm volatile("cp.async.cg.shared.global [%0], [%1], 16;" ::                 \
                 "r"(saddr), "l"(gptr))
#define CP_COMMIT() asm volatile("cp.async.commit_group;" ::: "memory")
#define CP_WAIT(n) asm volatile("cp.async.wait_group %0;" :: "n"(n) : "memory")

// ---------------- CSR build --------------------------------------------------
__global__ void k_zero_counts() {
    for (int i = blockIdx.x * blockDim.x + threadIdx.x; i <= NNODES;
         i += gridDim.x * blockDim.x)
        g_cursor[i] = 0;
}
__global__ void k_hist(const int* __restrict__ row) {
    for (int e = blockIdx.x * blockDim.x + threadIdx.x; e < NEDGES;
         e += gridDim.x * blockDim.x)
        atomicAdd(&g_cursor[row[e]], 1);
}
__global__ void k_scan() {
    __shared__ int s[1024];
    const int CH = (NNODES + 1023) / 1024;
    int t = threadIdx.x;
    int beg = t * CH;
    int end = min(NNODES, beg + CH);
    int mysum = 0;
    for (int i = beg; i < end; i++) mysum += g_cursor[i];
    s[t] = mysum;
    __syncthreads();
    for (int off = 1; off < 1024; off <<= 1) {
        int v = (t >= off) ? s[t - off] : 0;
        __syncthreads();
        s[t] += v;
        __syncthreads();
    }
    int run = s[t] - mysum;
    for (int i = beg; i < end; i++) {
        g_rowptr[i] = run;
        run += g_cursor[i];
    }
    if (t == 1023) g_rowptr[NNODES] = s[1023];
}
__global__ void k_reset_cursor() {
    for (int i = blockIdx.x * blockDim.x + threadIdx.x; i <= NNODES;
         i += gridDim.x * blockDim.x)
        g_cursor[i] = g_rowptr[i];
}
__global__ void k_scatter(const int* __restrict__ row, const int* __restrict__ col,
                          const float* __restrict__ vals) {
    for (int e = blockIdx.x * blockDim.x + threadIdx.x; e < NEDGES;
         e += gridDim.x * blockDim.x) {
        int p = atomicAdd(&g_cursor[row[e]], 1);
        g_cols[p] = col[e];
        g_vals[p] = vals[e];
    }
}

// ---------------- bf16 split converts ---------------------------------------
__global__ void k_convA(const float* __restrict__ src, int M, int K) {
    int idx = blockIdx.x * blockDim.x + threadIdx.x;
    int m = idx >> 8;
    int k2 = (idx & 255) * 2;
    if (m >= MPAD) return;
    float v0 = 0.f, v1 = 0.f;
    if (m < M) {
        if (k2 < K) v0 = src[(size_t)m * K + k2];
        if (k2 + 1 < K) v1 = src[(size_t)m * K + k2 + 1];
    }
    __nv_bfloat16 h0 = __float2bfloat16(v0);
    __nv_bfloat16 h1 = __float2bfloat16(v1);
    __nv_bfloat16 l0 = __float2bfloat16(v0 - __bfloat162float(h0));
    __nv_bfloat16 l1 = __float2bfloat16(v1 - __bfloat162float(h1));
    size_t o = ((size_t)m * KP + k2) >> 1;
    ((__nv_bfloat162*)g_Ahi)[o] = __nv_bfloat162(h0, h1);
    ((__nv_bfloat162*)g_Alo)[o] = __nv_bfloat162(l0, l1);
}

__global__ void k_convB(const float* __restrict__ W, int K, int N, int NP) {
    int idx = blockIdx.x * blockDim.x + threadIdx.x;
    int n = idx >> 9;
    int k = idx & (KP - 1);
    if (n >= NP) return;
    float v = (n < N && k < K) ? W[(size_t)k * N + n] : 0.f;
    __nv_bfloat16 h = __float2bfloat16(v);
    __nv_bfloat16 l = __float2bfloat16(v - __bfloat162float(h));
    g_Bhi[(size_t)n * KP + k] = h;
    g_Blo[(size_t)n * KP + k] = l;
}

// ---------------- HMMA bf16x3 GEMM, cp.async double-buffered ------------------
// Block 128x128, BK=32, 8 warps (2M x 4N), warp tile 64x32, mma m16n8k16.
// outMode 0: fp32 to C [Mact, Nact] (optional relu)
// outMode 1: bf16 to Cb [Mact, GP] (no relu in our uses)
#define GBM 128
#define GBN 128
#define STG_SZ 10240
#define OFF_AHI 0
#define OFF_ALO 20480
#define OFF_BHI 40960
#define OFF_BLO 61440
#define SM_TOTAL 81920

__global__ void __launch_bounds__(256, 2)
k_mma(const __nv_bfloat16* __restrict__ Ahi, const __nv_bfloat16* __restrict__ Alo,
      const __nv_bfloat16* __restrict__ Bhi, const __nv_bfloat16* __restrict__ Blo,
      float* __restrict__ C, __nv_bfloat16* __restrict__ Cb,
      int Mact, int Nact, int relu, int outMode) {
    extern __shared__ char smem[];
    uint32_t sb = smem_u32(smem);

    int tid = threadIdx.x, lane = tid & 31, w = tid >> 5;
    int wm = w >> 2, wn = w & 3;
    int rowBase = blockIdx.y * GBM, colBase = blockIdx.x * GBN;

    float acc[4][4][4];
#pragma unroll
    for (int i = 0; i < 4; i++)
#pragma unroll
        for (int j = 0; j < 4; j++)
#pragma unroll
            for (int c = 0; c < 4; c++) acc[i][j][c] = 0.f;

    int arow = lane & 15;
    int acolH = (lane >> 4) * 8;
    int l16 = lane & 15;
    int brow = l16 & 7;
    int bcolH = (l16 >> 3) * 8;

    int lr0 = tid >> 2;
    int lk = (tid & 3) * 16;

#define LOAD_CHUNK(ch, stg)                                                     \
    {                                                                           \
        int k0 = (ch) * 32;                                                     \
        _Pragma("unroll")                                                       \
        for (int it = 0; it < 2; it++) {                                        \
            int r = it * 64 + lr0;                                              \
            uint32_t so = (stg) * STG_SZ + r * 80 + lk;                         \
            const char* gh = (const char*)(Ahi + (size_t)(rowBase + r) * KP + k0); \
            const char* gl = (const char*)(Alo + (size_t)(rowBase + r) * KP + k0); \
            CP_ASYNC16(sb + OFF_AHI + so, gh + lk);                             \
            CP_ASYNC16(sb + OFF_ALO + so, gl + lk);                             \
            const char* bh_ = (const char*)(Bhi + (size_t)(colBase + r) * KP + k0); \
            const char* bl_ = (const char*)(Blo + (size_t)(colBase + r) * KP + k0); \
            CP_ASYNC16(sb + OFF_BHI + so, bh_ + lk);                            \
            CP_ASYNC16(sb + OFF_BLO + so, bl_ + lk);                            \
        }                                                                       \
    }

    LOAD_CHUNK(0, 0);
    CP_COMMIT();

    for (int ch = 0; ch < 16; ch++) {
        int cur = ch & 1;
        if (ch + 1 < 16) {
            LOAD_CHUNK(ch + 1, cur ^ 1);
            CP_COMMIT();
            CP_WAIT(1);
        } else {
            CP_WAIT(0);
        }
        __syncthreads();
        uint32_t aHiB = sb + OFF_AHI + cur * STG_SZ;
        uint32_t aLoB = sb + OFF_ALO + cur * STG_SZ;
        uint32_t bHiB = sb + OFF_BHI + cur * STG_SZ;
        uint32_t bLoB = sb + OFF_BLO + cur * STG_SZ;
#pragma unroll
        for (int kk = 0; kk < 2; kk++) {
            int kbase = kk * 16;
            uint32_t ah[4][4], al[4][4], bh[4][2], bl[4][2];
#pragma unroll
            for (int mt = 0; mt < 4; mt++) {
                uint32_t ro = (wm * 64 + mt * 16 + arow) * 80 +
                              (kbase + acolH) * 2;
                LDSM4(ah[mt], aHiB + ro);
                LDSM4(al[mt], aLoB + ro);
            }
#pragma unroll
            for (int nt = 0; nt < 4; nt++) {
                uint32_t ro = (wn * 32 + nt * 8 + brow) * 80 +
                              (kbase + bcolH) * 2;
                LDSM2(bh[nt], bHiB + ro);
                LDSM2(bl[nt], bLoB + ro);
            }
#pragma unroll
            for (int mt = 0; mt < 4; mt++)
#pragma unroll
                for (int nt = 0; nt < 4; nt++) {
                    MMA_BF16(acc[mt][nt], ah[mt], bh[nt]);
                    MMA_BF16(acc[mt][nt], ah[mt], bl[nt]);
                    MMA_BF16(acc[mt][nt], al[mt], bh[nt]);
                }
        }
        __syncthreads();
    }
#undef LOAD_CHUNK

#pragma unroll
    for (int mt = 0; mt < 4; mt++) {
#pragma unroll
        for (int nt = 0; nt < 4; nt++) {
            int r0 = rowBase + wm * 64 + mt * 16 + (lane >> 2);
            int c0 = colBase + wn * 32 + nt * 8 + (lane & 3) * 2;
            int r1 = r0 + 8;
            float* a = acc[mt][nt];
            if (relu) {
                a[0] = fmaxf(a[0], 0.f);
                a[1] = fmaxf(a[1], 0.f);
                a[2] = fmaxf(a[2], 0.f);
                a[3] = fmaxf(a[3], 0.f);
            }
            if (outMode) {
                // bf16 output, row stride GP; c0 even and Nact even so pair-guard ok
                if (c0 + 1 < Nact) {
                    if (r0 < Mact)
                        *(__nv_bfloat162*)(Cb + (size_t)r0 * GP + c0) =
                            __floats2bfloat162_rn(a[0], a[1]);
                    if (r1 < Mact)
                        *(__nv_bfloat162*)(Cb + (size_t)r1 * GP + c0) =
                            __floats2bfloat162_rn(a[2], a[3]);
                }
            } else {
                if (r0 < Mact && c0 + 1 < Nact)
                    *(float2*)(C + (size_t)r0 * Nact + c0) = make_float2(a[0], a[1]);
                else if (r0 < Mact && c0 < Nact)
                    C[(size_t)r0 * Nact + c0] = a[0];
                if (r1 < Mact && c0 + 1 < Nact)
                    *(float2*)(C + (size_t)r1 * Nact + c0) = make_float2(a[2], a[3]);
                else if (r1 < Mact && c0 < Nact)
                    C[(size_t)r1 * Nact + c0] = a[2];
            }
        }
    }
}

// ---------------- SpMM width-500, bf16 gather -> bf16 hi/lo split out ----------
// acc = sum val * bf16(in[col]); then optional relu, optional mix with fp32 tra;
// writes Ahi/Alo [r, KP] with zero padding in cols 500..511.
__global__ void __launch_bounds__(128)
k_spmmb_split(const __nv_bfloat16* __restrict__ Min, const float* __restrict__ mix,
              int relu) {
    const int W = 500;
    int r = blockIdx.x;
    int t = threadIdx.x;
    int start = g_rowptr[r], end = g_rowptr[r + 1];
    float4 acc = make_float4(0.f, 0.f, 0.f, 0.f);
    __shared__ int scol[128];
    __shared__ float sval[128];
    for (int e0 = start; e0 < end; e0 += 128) {
        int n = min(128, end - e0);
        if (t < n) {
            scol[t] = g_cols[e0 + t];
            sval[t] = g_vals[e0 + t];
        }
        __syncthreads();
        if (t < 125) {
            for (int i = 0; i < n; i++) {
                const uint2* p = (const uint2*)(Min + (size_t)scol[i] * GP) + t;
                float v = sval[i];
                uint2 q = *p;
                float2 f0 = __bfloat1622float2(*(__nv_bfloat162*)&q.x);
                float2 f1 = __bfloat1622float2(*(__nv_bfloat162*)&q.y);
                acc.x += v * f0.x;
                acc.y += v * f0.y;
                acc.z += v * f1.x;
                acc.w += v * f1.y;
            }
        }
        __syncthreads();
    }
    __nv_bfloat162* ph = (__nv_bfloat162*)(g_Ahi + (size_t)r * KP);
    __nv_bfloat162* pl = (__nv_bfloat162*)(g_Alo + (size_t)r * KP);
    if (t < 125) {
        if (relu) {
            acc.x = fmaxf(acc.x, 0.f);
            acc.y = fmaxf(acc.y, 0.f);
            acc.z = fmaxf(acc.z, 0.f);
            acc.w = fmaxf(acc.w, 0.f);
        }
        if (mix) {
            float4 mx = *((const float4*)(mix + (size_t)r * W) + t);
            acc.x = 0.5f * (acc.x + mx.x);
            acc.y = 0.5f * (acc.y + mx.y);
            acc.z = 0.5f * (acc.z + mx.z);
            acc.w = 0.5f * (acc.w + mx.w);
        }
        __nv_bfloat16 h0 = __float2bfloat16(acc.x);
        __nv_bfloat16 h1 = __float2bfloat16(acc.y);
        __nv_bfloat16 h2 = __float2bfloat16(acc.z);
        __nv_bfloat16 h3 = __float2bfloat16(acc.w);
        ph[2 * t + 0] = __nv_bfloat162(h0, h1);
        ph[2 * t + 1] = __nv_bfloat162(h2, h3);
        pl[2 * t + 0] = __nv_bfloat162(
            __float2bfloat16(acc.x - __bfloat162float(h0)),
            __float2bfloat16(acc.y - __bfloat162float(h1)));
        pl[2 * t + 1] = __nv_bfloat162(
            __float2bfloat16(acc.z - __bfloat162float(h2)),
            __float2bfloat16(acc.w - __bfloat162float(h3)));
    } else {
        __nv_bfloat162 zz(__float2bfloat16(0.f), __float2bfloat16(0.f));
        ph[2 * t + 0] = zz;
        ph[2 * t + 1] = zz;
        pl[2 * t + 0] = zz;
        pl[2 * t + 1] = zz;
    }
}

// ---------------- SpMM width-500, bf16 gather -> bf16 out (relu+mix fused) -----
__global__ void __launch_bounds__(128)
k_spmmb_b16(const __nv_bfloat16* __restrict__ Min, const float* __restrict__ mix,
            __nv_bfloat16* __restrict__ OutB, int relu) {
    const int W = 500;
    int r = blockIdx.x;
    int t = threadIdx.x;
    int start = g_rowptr[r], end = g_rowptr[r + 1];
    float4 acc = make_float4(0.f, 0.f, 0.f, 0.f);
    __shared__ int scol[128];
    __shared__ float sval[128];
    for (int e0 = start; e0 < end; e0 += 128) {
        int n = min(128, end - e0);
        if (t < n) {
            scol[t] = g_cols[e0 + t];
            sval[t] = g_vals[e0 + t];
        }
        __syncthreads();
        if (t < 125) {
            for (int i = 0; i < n; i++) {
                const uint2* p = (const uint2*)(Min + (size_t)scol[i] * GP) + t;
                float v = sval[i];
                uint2 q = *p;
                float2 f0 = __bfloat1622float2(*(__nv_bfloat162*)&q.x);
                float2 f1 = __bfloat1622float2(*(__nv_bfloat162*)&q.y);
                acc.x += v * f0.x;
                acc.y += v * f0.y;
                acc.z += v * f1.x;
                acc.w += v * f1.y;
            }
        }
        __syncthreads();
    }
    if (t < 125) {
        if (relu) {
            acc.x = fmaxf(acc.x, 0.f);
            acc.y = fmaxf(acc.y, 0.f);
            acc.z = fmaxf(acc.z, 0.f);
            acc.w = fmaxf(acc.w, 0.f);
        }
        if (mix) {
            float4 mx = *((const float4*)(mix + (size_t)r * W) + t);
            acc.x = 0.5f * (acc.x + mx.x);
            acc.y = 0.5f * (acc.y + mx.y);
            acc.z = 0.5f * (acc.z + mx.z);
            acc.w = 0.5f * (acc.w + mx.w);
        }
        uint2 o;
        *(__nv_bfloat162*)&o.x = __floats2bfloat162_rn(acc.x, acc.y);
        *(__nv_bfloat162*)&o.y = __floats2bfloat162_rn(acc.z, acc.w);
        *((uint2*)(OutB + (size_t)r * GP) + t) = o;
    }
}

// ---------------- SpMM width-10 -----------------------------------------------
__global__ void k_spmm_w10(const float* __restrict__ Min, float* __restrict__ Mout,
                           int relu) {
    int r = blockIdx.x * blockDim.x + threadIdx.x;
    if (r >= NNODES) return;
    float acc[10];
#pragma unroll
    for (int j = 0; j < 10; j++) acc[j] = 0.f;
    int start = g_rowptr[r], end = g_rowptr[r + 1];
    for (int e = start; e < end; e++) {
        int c = g_cols[e];
        float v = g_vals[e];
        const float2* p = (const float2*)(Min + (size_t)c * 10);
#pragma unroll
        for (int j = 0; j < 5; j++) {
            float2 x = p[j];
            acc[2 * j + 0] += v * x.x;
            acc[2 * j + 1] += v * x.y;
        }
    }
    float* o = Mout + (size_t)r * 10;
#pragma unroll
    for (int j = 0; j < 10; j++) o[j] = relu ? fmaxf(acc[j], 0.f) : acc[j];
}

// ---------------- thin GEMM layer4 ----------------------------------------------
__global__ void __launch_bounds__(256)
k_gemm_thin(const float* __restrict__ Hin, const float* __restrict__ Tmix,
            const float* __restrict__ W4, float* __restrict__ Mout) {
    const int K = 2000, CHUNK = 1000;
    __shared__ float Ws[CHUNK * 10];
    int tid = threadIdx.x;
    int r = blockIdx.x * 256 + tid;
    float acc[10];
#pragma unroll
    for (int j = 0; j < 10; j++) acc[j] = 0.f;
    for (int k0 = 0; k0 < K; k0 += CHUNK) {
        __syncthreads();
        for (int i = tid; i < CHUNK * 10; i += 256) Ws[i] = W4[k0 * 10 + i];
        __syncthreads();
        if (r < NNODES) {
            const float* hrow = Hin + (size_t)r * K + k0;
            const float* trow = Tmix + (size_t)r * K + k0;
            for (int k = 0; k < CHUNK; k += 4) {
                float4 h = *(const float4*)(hrow + k);
                float4 t = *(const float4*)(trow + k);
                float a0 = 0.5f * (h.x + t.x);
                float a1 = 0.5f * (h.y + t.y);
                float a2 = 0.5f * (h.z + t.z);
                float a3 = 0.5f * (h.w + t.w);
#pragma unroll
                for (int j = 0; j < 10; j++)
                    acc[j] += a0 * Ws[(k + 0) * 10 + j] + a1 * Ws[(k + 1) * 10 + j] +
                              a2 * Ws[(k + 2) * 10 + j] + a3 * Ws[(k + 3) * 10 + j];
            }
        }
    }
    if (r < NNODES) {
        float* o = Mout + (size_t)r * 10;
#pragma unroll
        for (int j = 0; j < 10; j++) o[j] = acc[j];
    }
}

// ---------------- tiny GEMM layer5 ----------------------------------------------
__global__ void k_gemm5(const float* __restrict__ Hin, const float* __restrict__ Zmix,
                        const float* __restrict__ W5, float* __restrict__ Mout) {
    __shared__ float Ws[100];
    int t = threadIdx.x;
    if (t < 100) Ws[t] = W5[t];
    __syncthreads();
    int r = blockIdx.x * blockDim.x + t;
    if (r >= NNODES) return;
    float a[10];
#pragma unroll
    for (int k = 0; k < 10; k++)
        a[k] = 0.5f * (Hin[(size_t)r * 10 + k] + Zmix[(size_t)r * 10 + k]);
    float* o = Mout + (size_t)r * 10;
#pragma unroll
    for (int j = 0; j < 10; j++) {
        float s = 0.f;
#pragma unroll
        for (int k = 0; k < 10; k++) s += a[k] * Ws[k * 10 + j];
        o[j] = s;
    }
}

// ---------------- row softmax over width 10 --------------------------------------
__global__ void k_softmax(const float* __restrict__ S, float* __restrict__ out) {
    int r = blockIdx.x * blockDim.x + threadIdx.x;
    if (r >= NNODES) return;
    float v[10];
    float m = -1e30f;
#pragma unroll
    for (int j = 0; j < 10; j++) {
        v[j] = S[(size_t)r * 10 + j];
        m = fmaxf(m, v[j]);
    }
    float sum = 0.f;
#pragma unroll
    for (int j = 0; j < 10; j++) {
        v[j] = expf(v[j] - m);
        sum += v[j];
    }
    float inv = 1.f / sum;
#pragma unroll
    for (int j = 0; j < 10; j++) out[(size_t)r * 10 + j] = v[j] * inv;
}

// ---------------- launch ---------------------------------------------------------
extern "C" void kernel_launch(void* const* d_in, const int* in_sizes, int n_in,
                              void* d_out, int out_size) {
    const float* x    = (const float*)d_in[0];
    const float* tra1 = (const float*)d_in[1];
    const float* tra2 = (const float*)d_in[2];
    const float* tra3 = (const float*)d_in[3];
    const float* z    = (const float*)d_in[4];
    const float* evals = (const float*)d_in[5];
    const int*   row  = (const int*)d_in[6];
    const int*   col  = (const int*)d_in[7];
    const float* W1 = (const float*)d_in[8];
    const float* W2 = (const float*)d_in[9];
    const float* W3 = (const float*)d_in[10];
    const float* W4 = (const float*)d_in[11];
    const float* W5 = (const float*)d_in[12];
    float* out = (float*)d_out;

    float *bufA, *bufS0, *bufS1;
    __nv_bfloat16 *Ahi, *Alo, *Bhi, *Blo, *G, *G2;
    cudaGetSymbolAddress((void**)&bufA, g_bufA);
    cudaGetSymbolAddress((void**)&bufS0, g_bufS0);
    cudaGetSymbolAddress((void**)&bufS1, g_bufS1);
    cudaGetSymbolAddress((void**)&Ahi, g_Ahi);
    cudaGetSymbolAddress((void**)&Alo, g_Alo);
    cudaGetSymbolAddress((void**)&Bhi, g_Bhi);
    cudaGetSymbolAddress((void**)&Blo, g_Blo);
    cudaGetSymbolAddress((void**)&G, g_G);
    cudaGetSymbolAddress((void**)&G2, g_G2);

    cudaFuncSetAttribute(k_mma, cudaFuncAttributeMaxDynamicSharedMemorySize,
                         SM_TOTAL);

    const int MT = 391;

    // L1 prep — k_mma is the 4th launch (ncu capture slot)
    k_convA<<<MPAD, 256>>>(x, NNODES, 512);
    k_convB<<<1024, 256>>>(W1, 512, 500, 512);
    k_zero_counts<<<64, 256>>>();
    // L1: B1 = x @ W1  -> bf16 gather buffer
    k_mma<<<dim3(4, MT), 256, SM_TOTAL>>>(Ahi, Alo, Bhi, Blo, nullptr, G,
                                          NNODES, 500, 0, 1);
    // CSR build
    k_hist<<<2048, 256>>>(row);
    k_scan<<<1, 1024>>>();
    k_reset_cursor<<<64, 256>>>();
    k_scatter<<<2048, 256>>>(row, col, evals);

    // L1->L2: A2 = split(0.5*(relu(spmm(B1)) + tra1))
    k_spmmb_split<<<NNODES, 128>>>(G, tra1, 1);

    // L2: B2 = A2 @ W2 -> bf16 gather buffer
    k_convB<<<1024, 256>>>(W2, 500, 500, 512);
    k_mma<<<dim3(4, MT), 256, SM_TOTAL>>>(Ahi, Alo, Bhi, Blo, nullptr, G,
                                          NNODES, 500, 0, 1);

    // L2->L3: M3 = 0.5*(relu(spmm(B2)) + tra2) -> bf16 G2
    k_spmmb_b16<<<NNODES, 128>>>(G, tra2, G2, 1);
    // S3 = spmm(M3) -> split (no relu/mix)
    k_spmmb_split<<<NNODES, 128>>>(G2, nullptr, 0);

    // L3: H3 = relu(S3 @ W3) -> fp32 bufA [N=2000]
    k_convB<<<4096, 256>>>(W3, 500, 2000, 2048);
    k_mma<<<dim3(16, MT), 256, SM_TOTAL>>>(Ahi, Alo, Bhi, Blo, bufA, nullptr,
                                           NNODES, 2000, 1, 0);

    // L4: B4 = (0.5*(H3+tra3)) @ W4 ; H4 = relu(spmm10(B4))
    k_gemm_thin<<<(NNODES + 255) / 256, 256>>>(bufA, tra3, W4, bufS0);
    k_spmm_w10<<<(NNODES + 255) / 256, 256>>>(bufS0, bufS1, 1);

    // L5
    k_gemm5<<<(NNODES + 255) / 256, 256>>>(bufS1, z, W5, bufS0);
    k_spmm_w10<<<(NNODES + 255) / 256, 256>>>(bufS0, bufS1, 0);
    k_softmax<<<(NNODES + 255) / 256, 256>>>(bufS1, out);
}